// round 16
// baseline (speedup 1.0000x reference)
#include <cuda_runtime.h>
#include <cuda_bf16.h>
#include <math.h>
#include <stdint.h>

// B=128, T=64, IN=512, CTRL=512, N=128, MM=128, S=3, R=4, W=1
#define NB 128u

// ---------------- persistent device state ----------------
__device__ float g_p1x[2 * 16 * 128 * 512];                     // x-half gemm1 partials, double-buffered
__device__ float g_p1r[16 * 128 * 512];                         // rv-half gemm1 partials
__device__ float g_part2[8 * 128 * 960];                        // gemm2 partials
__device__ __align__(16) __nv_bfloat16 g_xh[128 * 64 * 512];
__device__ __align__(16) __nv_bfloat16 g_xl[128 * 64 * 512];
__device__ __align__(16) __nv_bfloat16 g_WcT_h[512 * 1024];     // Wc^T [n][k]
__device__ __align__(16) __nv_bfloat16 g_WcT_l[512 * 1024];
__device__ __align__(16) __nv_bfloat16 g_WkT_h[960 * 512];      // Wk^T [n][k], rows>=926 zero
__device__ __align__(16) __nv_bfloat16 g_WkT_l[960 * 512];
__device__ __align__(16) __nv_bfloat16 g_acth[128 * 512];
__device__ __align__(16) __nv_bfloat16 g_actl[128 * 512];
__device__ __align__(16) __nv_bfloat16 g_rvh[128 * 512];
__device__ __align__(16) __nv_bfloat16 g_rvl[128 * 512];
__device__ unsigned g_barrier;

// ---------------- helpers ----------------
__device__ __forceinline__ uint32_t smem_u32(const void* p) {
    uint32_t a;
    asm("{ .reg .u64 t; cvta.to.shared.u64 t, %1; cvt.u32.u64 %0, t; }" : "=r"(a) : "l"(p));
    return a;
}
__device__ __forceinline__ void ldmatrix_x4(uint32_t& r0, uint32_t& r1, uint32_t& r2, uint32_t& r3, uint32_t addr) {
    asm volatile("ldmatrix.sync.aligned.m8n8.x4.shared.b16 {%0,%1,%2,%3}, [%4];"
                 : "=r"(r0), "=r"(r1), "=r"(r2), "=r"(r3) : "r"(addr));
}
__device__ __forceinline__ void mma_bf16(float* c, const uint32_t* a, uint32_t b0, uint32_t b1) {
    asm volatile("mma.sync.aligned.m16n8k16.row.col.f32.bf16.bf16.f32 "
                 "{%0,%1,%2,%3}, {%4,%5,%6,%7}, {%8,%9}, {%0,%1,%2,%3};"
                 : "+f"(c[0]), "+f"(c[1]), "+f"(c[2]), "+f"(c[3])
                 : "r"(a[0]), "r"(a[1]), "r"(a[2]), "r"(a[3]), "r"(b0), "r"(b1));
}
static __device__ __forceinline__ void bf16_split(float v, __nv_bfloat16& h, __nv_bfloat16& l) {
    h = __float2bfloat16(v);
    l = __float2bfloat16(v - __bfloat162float(h));
}

// ---------------- prep kernels ----------------
__global__ void prep_x_kernel(const float* __restrict__ x) {
    int i = blockIdx.x * blockDim.x + threadIdx.x;
    int st = gridDim.x * blockDim.x;
    for (int j = i; j < 128 * 64 * 512; j += st) {
        __nv_bfloat16 h, l; bf16_split(x[j], h, l);
        g_xh[j] = h; g_xl[j] = l;
    }
    for (int j = i; j < 128 * 512; j += st) {
        g_rvh[j] = __float2bfloat16(0.0f);
        g_rvl[j] = __float2bfloat16(0.0f);
    }
    if (i == 0) g_barrier = 0u;
}
__global__ void prep_w_kernel(const float* __restrict__ Wc, const float* __restrict__ Wk) {
    int i = blockIdx.x * blockDim.x + threadIdx.x;
    int st = gridDim.x * blockDim.x;
    for (int j = i; j < 512 * 1024; j += st) {
        int n = j >> 10, k = j & 1023;
        __nv_bfloat16 h, l; bf16_split(Wc[k * 512 + n], h, l);
        g_WcT_h[j] = h; g_WcT_l[j] = l;
    }
    for (int j = i; j < 960 * 512; j += st) {
        int n = j >> 9, k = j & 511;
        float v = (n < 926) ? Wk[k * 926 + n] : 0.0f;
        __nv_bfloat16 h, l; bf16_split(v, h, l);
        g_WkT_h[j] = h; g_WkT_l[j] = l;
    }
}

// ---------------- counter grid barrier ----------------
__device__ __forceinline__ void grid_sync(unsigned target) {
    __syncthreads();
    if (threadIdx.x == 0) {
        unsigned* bar = &g_barrier;
        asm volatile("red.release.gpu.global.add.u32 [%0], 1;" :: "l"(bar) : "memory");
        unsigned v;
        do {
            asm volatile("ld.relaxed.gpu.global.b32 %0, [%1];" : "=r"(v) : "l"(bar) : "memory");
        } while (v < target);
        asm volatile("fence.acq_rel.gpu;" ::: "memory");
    }
    __syncthreads();
}

// ---------------- staging ----------------
// 144B-stride tiles (K=64): 8 quads/row
__device__ __forceinline__ void stage_A144(const __nv_bfloat16* __restrict__ srcH,
                                           const __nv_bfloat16* __restrict__ srcL,
                                           size_t rstride, char* tAh, char* tAl, int tid) {
#pragma unroll
    for (int it = 0; it < 2; it++) {
        int q = tid + it * 512;
        int r = q >> 3, qq = q & 7;
        uint4 vh = *(const uint4*)((const char*)(srcH + (size_t)r * rstride) + qq * 16);
        uint4 vl = *(const uint4*)((const char*)(srcL + (size_t)r * rstride) + qq * 16);
        *(uint4*)(tAh + r * 144 + qq * 16) = vh;
        *(uint4*)(tAl + r * 144 + qq * 16) = vl;
    }
}
__device__ __forceinline__ void stage_B144(const __nv_bfloat16* __restrict__ srcH,
                                           const __nv_bfloat16* __restrict__ srcL,
                                           size_t rstride, char* tBh, char* tBl, int tid) {
    int r = tid >> 3, qq = tid & 7;
    uint4 vh = *(const uint4*)((const char*)(srcH + (size_t)r * rstride) + qq * 16);
    uint4 vl = *(const uint4*)((const char*)(srcL + (size_t)r * rstride) + qq * 16);
    *(uint4*)(tBh + r * 144 + qq * 16) = vh;
    *(uint4*)(tBl + r * 144 + qq * 16) = vl;
}
// 80B-stride tiles (K=32): 4 quads/row
__device__ __forceinline__ void stage80_A(const __nv_bfloat16* __restrict__ srcH,
                                          const __nv_bfloat16* __restrict__ srcL,
                                          size_t rstride, char* tH, char* tL, int tid) {
    int r = tid >> 2, qq = tid & 3;        // 128 rows x 4 quads
    uint4 vh = *(const uint4*)((const char*)(srcH + (size_t)r * rstride) + qq * 16);
    uint4 vl = *(const uint4*)((const char*)(srcL + (size_t)r * rstride) + qq * 16);
    *(uint4*)(tH + r * 80 + qq * 16) = vh;
    *(uint4*)(tL + r * 80 + qq * 16) = vl;
}
__device__ __forceinline__ void stage80_B(const __nv_bfloat16* __restrict__ srcH,
                                          const __nv_bfloat16* __restrict__ srcL,
                                          size_t rstride, char* tH, char* tL, int tid) {
    if (tid < 256) {
        int r = tid >> 2, qq = tid & 3;    // 64 rows x 4 quads
        uint4 vh = *(const uint4*)((const char*)(srcH + (size_t)r * rstride) + qq * 16);
        uint4 vl = *(const uint4*)((const char*)(srcL + (size_t)r * rstride) + qq * 16);
        *(uint4*)(tH + r * 80 + qq * 16) = vh;
        *(uint4*)(tL + r * 80 + qq * 16) = vl;
    }
}

// ---------------- HMMA 128x64, K=64, 3 passes (GEMM2) ----------------
__device__ __forceinline__ void gemm_tile_hmma(
    uint32_t aAh, uint32_t aAl, uint32_t aBh, uint32_t aBl,
    float* __restrict__ dst, int ldw, int lane, int wid) {
    const int wm = (wid & 7) * 16;
    const int wn = (wid >> 3) * 32;
    const uint32_t aBase = (uint32_t)(wm + (lane & 15)) * 144u + (uint32_t)((lane >> 4) * 16);
    const int l8 = lane & 7, sel = lane >> 3;
    const uint32_t bBase = (uint32_t)(wn + l8 + ((sel >> 1) * 8)) * 144u + (uint32_t)((sel & 1) * 16);

    uint32_t Ah[4][4], Al[4][4];
#pragma unroll
    for (int ks = 0; ks < 4; ks++) {
        ldmatrix_x4(Ah[ks][0], Ah[ks][1], Ah[ks][2], Ah[ks][3], aAh + aBase + ks * 32);
        ldmatrix_x4(Al[ks][0], Al[ks][1], Al[ks][2], Al[ks][3], aAl + aBase + ks * 32);
    }
    float acc[4][4] = {};
#pragma unroll
    for (int p = 0; p < 3; p++) {
        uint32_t aB = (p == 2) ? aBl : aBh;
        const uint32_t (*A)[4] = (p == 1) ? Al : Ah;
#pragma unroll
        for (int ks = 0; ks < 4; ks++) {
#pragma unroll
            for (int nf = 0; nf < 2; nf++) {
                uint32_t b0, b1, b2, b3;
                ldmatrix_x4(b0, b1, b2, b3, aB + bBase + nf * (16 * 144) + ks * 32);
                mma_bf16(acc[nf * 2 + 0], A[ks], b0, b1);
                mma_bf16(acc[nf * 2 + 1], A[ks], b2, b3);
            }
        }
    }
    const int row = wm + (lane >> 2);
    const int colb = (lane & 3) * 2;
#pragma unroll
    for (int nf2 = 0; nf2 < 4; nf2++) {
        int col = wn + nf2 * 8 + colb;
        *(float2*)&dst[(size_t)row * ldw + col] = make_float2(acc[nf2][0], acc[nf2][1]);
        *(float2*)&dst[(size_t)(row + 8) * ldw + col] = make_float2(acc[nf2][2], acc[nf2][3]);
    }
}

// ---------------- HMMA 128x64, K=32, 3 passes (GEMM1 thin slices, 80B stride) ----------------
__device__ __forceinline__ void gemm32_hmma(
    uint32_t aAh, uint32_t aAl, uint32_t aBh, uint32_t aBl,
    float* __restrict__ dst, int lane, int wid) {
    const int wm = (wid & 7) * 16;
    const int wn = (wid >> 3) * 32;
    const uint32_t aBase = (uint32_t)(wm + (lane & 15)) * 80u + (uint32_t)((lane >> 4) * 16);
    const int l8 = lane & 7, sel = lane >> 3;
    const uint32_t bBase = (uint32_t)(wn + l8 + ((sel >> 1) * 8)) * 80u + (uint32_t)((sel & 1) * 16);

    uint32_t Ah[2][4], Al[2][4];
#pragma unroll
    for (int ks = 0; ks < 2; ks++) {
        ldmatrix_x4(Ah[ks][0], Ah[ks][1], Ah[ks][2], Ah[ks][3], aAh + aBase + ks * 32);
        ldmatrix_x4(Al[ks][0], Al[ks][1], Al[ks][2], Al[ks][3], aAl + aBase + ks * 32);
    }
    float acc[4][4] = {};
#pragma unroll
    for (int p = 0; p < 3; p++) {
        uint32_t aB = (p == 2) ? aBl : aBh;
        const uint32_t (*A)[4] = (p == 1) ? Al : Ah;
#pragma unroll
        for (int ks = 0; ks < 2; ks++) {
#pragma unroll
            for (int nf = 0; nf < 2; nf++) {
                uint32_t b0, b1, b2, b3;
                ldmatrix_x4(b0, b1, b2, b3, aB + bBase + nf * (16 * 80) + ks * 32);
                mma_bf16(acc[nf * 2 + 0], A[ks], b0, b1);
                mma_bf16(acc[nf * 2 + 1], A[ks], b2, b3);
            }
        }
    }
    const int row = wm + (lane >> 2);
    const int colb = (lane & 3) * 2;
#pragma unroll
    for (int nf2 = 0; nf2 < 4; nf2++) {
        int col = wn + nf2 * 8 + colb;
        *(float2*)&dst[(size_t)row * 512 + col] = make_float2(acc[nf2][0], acc[nf2][1]);
        *(float2*)&dst[(size_t)(row + 8) * 512 + col] = make_float2(acc[nf2][2], acc[nf2][3]);
    }
}

// ---------------- the persistent kernel (512 threads, 128 CTAs) ----------------
__global__ void __launch_bounds__(512) ntm_persistent(
    const float* __restrict__ bc, const float* __restrict__ bk,
    float* __restrict__ dout) {
    extern __shared__ float smem[];
    float* sM   = smem;            // 128*132 = 16896 (Mem, persistent)
    float* s_w  = smem + 16896;    // 640
    float* s_cn = smem + 17536;    // 512

    uint32_t base_u32 = smem_u32(smem);
    uint32_t tiles_u32 = (base_u32 + 18048u * 4u + 1023u) & ~1023u;
    char* tiles = (char*)smem + (tiles_u32 - base_u32);
    // K=32 tiles (80B stride)
    char* tAx_h  = tiles;              uint32_t aAx_h  = tiles_u32;
    char* tAx_l  = tiles + 10240;      uint32_t aAx_l  = tiles_u32 + 10240;
    char* tAr_h  = tiles + 20480;      uint32_t aAr_h  = tiles_u32 + 20480;
    char* tAr_l  = tiles + 30720;      uint32_t aAr_l  = tiles_u32 + 30720;
    char* tB1x_h = tiles + 40960;      uint32_t aB1x_h = tiles_u32 + 40960;
    char* tB1x_l = tiles + 46080;      uint32_t aB1x_l = tiles_u32 + 46080;
    char* tB1r_h = tiles + 51200;      uint32_t aB1r_h = tiles_u32 + 51200;
    char* tB1r_l = tiles + 56320;      uint32_t aB1r_l = tiles_u32 + 56320;
    // K=64 tiles (144B stride) for GEMM2
    char* tA2_h  = tiles + 61440;      uint32_t aA2_h  = tiles_u32 + 61440;
    char* tA2_l  = tiles + 79872;      uint32_t aA2_l  = tiles_u32 + 79872;
    char* tB2_h  = tiles + 98304;      uint32_t aB2_h  = tiles_u32 + 98304;
    char* tB2_l  = tiles + 107520;     uint32_t aB2_l  = tiles_u32 + 107520;
    float* scratch = (float*)tA2_h;    // heads scratch aliases GEMM2 A tiles (dead then)

    const int tid = threadIdx.x;
    const int wid = tid >> 5, lane = tid & 31;
    const int e = blockIdx.x;

    // per-CTA state init
    for (int i = tid; i < 128 * 128; i += 512) {
        int n = i >> 7, m = i & 127;
        sM[n * 132 + m] = (n == 64) ? 1.0f : 0.0f;
    }
    for (int i = tid; i < 640; i += 512) s_w[i] = 0.0f;
    __syncthreads();
    {
        int m = tid & 127, qt = tid >> 7;
        float cs = 0.0f;
        int n0 = qt * 32;
#pragma unroll 8
        for (int n = n0; n < n0 + 32; n++) { float v = sM[n * 132 + m]; cs += v * v; }
        s_cn[qt * 128 + m] = cs;
    }

    // tile coordinates
    const int c1   = (e & 7) * 64;           // GEMM1 coltile
    const int s1   = e >> 3;                 // GEMM1 K-split (0..15)
    const int k0   = s1 * 32;                // K offset within x-half / rv-half
    const int g2_n0 = (e % 15) * 64;
    const int g2_sp = e / 15;
    const int g2_k0 = g2_sp * 64;

    // resident B tiles
    stage80_B(g_WcT_h + (size_t)c1 * 1024 + k0, g_WcT_l + (size_t)c1 * 1024 + k0,
              1024, tB1x_h, tB1x_l, tid);
    if (tid >= 256 && tid < 512) {
        int t2 = tid - 256;
        int r = t2 >> 2, qq = t2 & 3;
        size_t src = (size_t)(c1 + r) * 1024 + 512 + k0 + qq * 8;
        *(uint4*)(tB1r_h + r * 80 + qq * 16) = *(const uint4*)(g_WcT_h + src);
        *(uint4*)(tB1r_l + r * 80 + qq * 16) = *(const uint4*)(g_WcT_l + src);
    }
    if (e < 120)
        stage_B144(g_WkT_h + (size_t)g2_n0 * 512 + g2_k0, g_WkT_l + (size_t)g2_n0 * 512 + g2_k0,
                   512, tB2_h, tB2_l, tid);
    // prologue: x-half GEMM for t=0 -> parity 0
    stage80_A(g_xh + (size_t)0 * 512 + k0, g_xl + (size_t)0 * 512 + k0, 64 * 512, tAx_h, tAx_l, tid);
    __syncthreads();
    gemm32_hmma(aAx_h, aAx_l, aB1x_h, aB1x_l,
                &g_p1x[(size_t)(0 * 16 + s1) * 65536 + c1], lane, wid);

    unsigned nsync = 0;

    for (int t = 0; t < 64; t++) {
        // =========== GEMM1 (rv-half only, K=32) ===========
        {
            stage80_A(g_rvh + k0, g_rvl + k0, 512, tAr_h, tAr_l, tid);
            __syncthreads();
            gemm32_hmma(aAr_h, aAr_l, aB1r_h, aB1r_l,
                        &g_p1r[(size_t)s1 * 65536 + c1], lane, wid);
        }
        grid_sync(++nsync * NB);

        // =========== ACT (+ x-half GEMM for t+1, parity (t+1)&1) ===========
        {
            if (t < 63)
                stage80_A(g_xh + (size_t)(t + 1) * 512 + k0, g_xl + (size_t)(t + 1) * 512 + k0,
                          64 * 512, tAx_h, tAx_l, tid);
            int j = tid;
            float s = bc[j];
            int par = t & 1;
#pragma unroll
            for (int sp = 0; sp < 16; sp++) s += g_p1x[(size_t)((par * 16 + sp) * 128 + e) * 512 + j];
#pragma unroll
            for (int sp = 0; sp < 16; sp++) s += g_p1r[(size_t)(sp * 128 + e) * 512 + j];
            float v = tanhf(s);
            dout[((size_t)e * 64 + t) * 512 + j] = v;
            __nv_bfloat16 h, l; bf16_split(v, h, l);
            g_acth[e * 512 + j] = h;
            g_actl[e * 512 + j] = l;
            __syncthreads();
            if (t < 63)
                gemm32_hmma(aAx_h, aAx_l, aB1x_h, aB1x_l,
                            &g_p1x[(size_t)(((t + 1) & 1) * 16 + s1) * 65536 + c1], lane, wid);
        }
        grid_sync(++nsync * NB);

        // =========== GEMM2 (B resident): part2 = act @ Wk ===========
        if (e < 120) {
            stage_A144(g_acth + g2_k0, g_actl + g2_k0, 512, tA2_h, tA2_l, tid);
            __syncthreads();
            gemm_tile_hmma(aA2_h, aA2_l, aB2_h, aB2_l,
                           &g_part2[(size_t)(g2_sp * 128) * 960 + g2_n0], 960, lane, wid);
        }
        grid_sync(++nsync * NB);

        // =========== HEADS (per-batch, SMEM-resident Mem, vectorized) ===========
        {
            float* s_instr = scratch;           // 928
            float* s_rsn   = scratch + 928;     // 128
            float* s_q     = scratch + 1056;    // 640
            float* s_p2    = scratch + 1696;    // 5*512 = 2560
            float* s_wi    = scratch + 4256;    // 640

            for (int j = tid; j < 926; j += 512) {
                float s = bk[j];
#pragma unroll
                for (int sp = 0; sp < 8; sp++) s += g_part2[(size_t)(sp * 128 + e) * 960 + j];
                s_instr[j] = s;
            }
            if (tid < 128)
                s_rsn[tid] = rsqrtf(fmaxf(s_cn[tid] + s_cn[128 + tid] + s_cn[256 + tid] + s_cn[384 + tid], 1e-12f));
            __syncthreads();

            if (wid < 5) {
                int basei = (wid < 4) ? wid * 134 : 536;
                float kv[4];
                float ks = 0.0f;
#pragma unroll
                for (int j = 0; j < 4; j++) { int m = lane * 4 + j; kv[j] = s_instr[basei + m]; ks += kv[j] * kv[j]; }
#pragma unroll
                for (int o = 16; o > 0; o >>= 1) ks += __shfl_xor_sync(0xffffffffu, ks, o);
                float rk = rsqrtf(fmaxf(ks, 1e-12f));
#pragma unroll
                for (int j = 0; j < 4; j++) { int m = lane * 4 + j; s_q[wid * 128 + m] = kv[j] * rk * s_rsn[m]; }
            }
            __syncthreads();

            {
                int n = tid & 127, qt = tid >> 7;
                const float* row = &sM[n * 132];
                int m0 = qt * 32;
                float a0 = 0, a1 = 0, a2 = 0, a3 = 0, a4 = 0;
#pragma unroll
                for (int mc = 0; mc < 32; mc += 4) {
                    int m = m0 + mc;
                    float4 rv4 = *(const float4*)&row[m];
                    float4 q0 = *(const float4*)&s_q[m];
                    float4 q1 = *(const float4*)&s_q[128 + m];
                    float4 q2 = *(const float4*)&s_q[256 + m];
                    float4 q3 = *(const float4*)&s_q[384 + m];
                    float4 q4 = *(const float4*)&s_q[512 + m];
                    a0 += rv4.x * q0.x + rv4.y * q0.y + rv4.z * q0.z + rv4.w * q0.w;
                    a1 += rv4.x * q1.x + rv4.y * q1.y + rv4.z * q1.z + rv4.w * q1.w;
                    a2 += rv4.x * q2.x + rv4.y * q2.y + rv4.z * q2.z + rv4.w * q2.w;
                    a3 += rv4.x * q3.x + rv4.y * q3.y + rv4.z * q3.z + rv4.w * q3.w;
                    a4 += rv4.x * q4.x + rv4.y * q4.y + rv4.z * q4.z + rv4.w * q4.w;
                }
                s_p2[0 * 512 + qt * 128 + n] = a0;
                s_p2[1 * 512 + qt * 128 + n] = a1;
                s_p2[2 * 512 + qt * 128 + n] = a2;
                s_p2[3 * 512 + qt * 128 + n] = a3;
                s_p2[4 * 512 + qt * 128 + n] = a4;
            }
            __syncthreads();

            if (wid < 5) {
                int basei = (wid < 4) ? wid * 134 : 536;
                float beta = expf(s_instr[basei + 128]);
                float gg = 1.0f / (1.0f + expf(-s_instr[basei + 129]));
                float a0 = s_instr[basei + 130], a1 = s_instr[basei + 131], a2 = s_instr[basei + 132];
                float mxs = fmaxf(a0, fmaxf(a1, a2));
                float e0 = expf(a0 - mxs), e1 = expf(a1 - mxs), e2 = expf(a2 - mxs);
                float esi = 1.0f / (e0 + e1 + e2);
                float sh0 = e0 * esi, sh1 = e1 * esi, sh2 = e2 * esi;
                float xt = s_instr[basei + 133];
                float tpow = fmaxf(xt, 0.0f) + log1pf(expf(-fabsf(xt))) + 1.0f;

                float vv[4];
                float mx = -3.4e38f;
#pragma unroll
                for (int j = 0; j < 4; j++) {
                    int n = lane * 4 + j;
                    vv[j] = (s_p2[wid * 512 + n] + s_p2[wid * 512 + 128 + n]
                           + s_p2[wid * 512 + 256 + n] + s_p2[wid * 512 + 384 + n]) * beta;
                    mx = fmaxf(mx, vv[j]);
                }
#pragma unroll
                for (int o = 16; o > 0; o >>= 1) mx = fmaxf(mx, __shfl_xor_sync(0xffffffffu, mx, o));
                float ee[4], se = 0.0f;
#pragma unroll
                for (int j = 0; j < 4; j++) { ee[j] = expf(vv[j] - mx); se += ee[j]; }
#pragma unroll
                for (int o = 16; o > 0; o >>= 1) se += __shfl_xor_sync(0xffffffffu, se, o);
                float sei = 1.0f / se;
#pragma unroll
                for (int j = 0; j < 4; j++) {
                    int n = lane * 4 + j;
                    float wold = s_w[wid * 128 + n];
                    s_wi[wid * 128 + n] = ee[j] * sei * gg + wold * (1.0f - gg);
                }
                __syncwarp();
                float pp[4], ps = 0.0f;
#pragma unroll
                for (int j = 0; j < 4; j++) {
                    int n = lane * 4 + j;
                    float ws = sh0 * s_wi[wid * 128 + ((n + 127) & 127)]
                             + sh1 * s_wi[wid * 128 + n]
                             + sh2 * s_wi[wid * 128 + ((n + 1) & 127)];
                    pp[j] = powf(ws, tpow);
                    ps += pp[j];
                }
#pragma unroll
                for (int o = 16; o > 0; o >>= 1) ps += __shfl_xor_sync(0xffffffffu, ps, o);
                float psi = 1.0f / (ps + 1e-12f);
#pragma unroll
                for (int j = 0; j < 4; j++) {
                    int n = lane * 4 + j;
                    s_w[wid * 128 + n] = pp[j] * psi;
                }
            }
            __syncthreads();

            {
                int m = tid & 127, qt = tid >> 7;
                float em = s_instr[670 + m];
                float am = s_instr[798 + m];
                float r0 = 0, r1 = 0, r2 = 0, r3 = 0, cs = 0;
                int n0 = qt * 32;
#pragma unroll
                for (int nc = n0; nc < n0 + 32; nc += 4) {
                    float4 ww4 = *(const float4*)&s_w[512 + nc];
                    float4 w0 = *(const float4*)&s_w[nc];
                    float4 w1 = *(const float4*)&s_w[128 + nc];
                    float4 w2 = *(const float4*)&s_w[256 + nc];
                    float4 w3 = *(const float4*)&s_w[384 + nc];
                    const float* ww = &ww4.x;
                    const float* p0 = &w0.x; const float* p1 = &w1.x;
                    const float* p2 = &w2.x; const float* p3 = &w3.x;
#pragma unroll
                    for (int u = 0; u < 4; u++) {
                        int n = nc + u;
                        float Mv = sM[n * 132 + m];
                        Mv = Mv * (1.0f - ww[u] * em) + ww[u] * am;
                        sM[n * 132 + m] = Mv;
                        cs += Mv * Mv;
                        r0 += Mv * p0[u]; r1 += Mv * p1[u];
                        r2 += Mv * p2[u]; r3 += Mv * p3[u];
                    }
                }
                s_cn[qt * 128 + m] = cs;
                s_p2[0 * 512 + qt * 128 + m] = r0;
                s_p2[1 * 512 + qt * 128 + m] = r1;
                s_p2[2 * 512 + qt * 128 + m] = r2;
                s_p2[3 * 512 + qt * 128 + m] = r3;
            }
            __syncthreads();
            if (tid < 128) {
#pragma unroll
                for (int r = 0; r < 4; r++) {
                    float rv = s_p2[r * 512 + tid] + s_p2[r * 512 + 128 + tid]
                             + s_p2[r * 512 + 256 + tid] + s_p2[r * 512 + 384 + tid];
                    __nv_bfloat16 h, l; bf16_split(rv, h, l);
                    g_rvh[e * 512 + r * 128 + tid] = h;
                    g_rvl[e * 512 + r * 128 + tid] = l;
                }
            }
        }
        grid_sync(++nsync * NB);
    }
}

// ---------------- launch ----------------
extern "C" void kernel_launch(void* const* d_in, const int* in_sizes, int n_in,
                              void* d_out, int out_size) {
    const float *x = nullptr, *Wc = nullptr, *bc = nullptr, *Wk = nullptr, *bk = nullptr;
    for (int i = 0; i < n_in; i++) {
        switch (in_sizes[i]) {
            case 128 * 64 * 512: x  = (const float*)d_in[i]; break;
            case 1024 * 512:     Wc = (const float*)d_in[i]; break;
            case 512:            bc = (const float*)d_in[i]; break;
            case 512 * 926:      Wk = (const float*)d_in[i]; break;
            case 926:            bk = (const float*)d_in[i]; break;
        }
    }

    // smem: 18048 floats persistent + align + 116736B tiles
    const int SMEM = 18048 * 4 + 1024 + 116736;  // 189952 B
    cudaFuncSetAttribute(ntm_persistent, cudaFuncAttributeMaxDynamicSharedMemorySize, SMEM);

    prep_x_kernel<<<2048, 256>>>(x);
    prep_w_kernel<<<1024, 256>>>(Wc, Wk);
    ntm_persistent<<<128, 512, SMEM>>>(bc, bk, (float*)d_out);
}

// round 17
// speedup vs baseline: 1.0733x; 1.0733x over previous
#include <cuda_runtime.h>
#include <cuda_bf16.h>
#include <math.h>
#include <stdint.h>

// B=128, T=64, IN=512, CTRL=512, N=128, MM=128, S=3, R=4, W=1
#define NB 128u

// ---------------- persistent device state ----------------
__device__ float g_part1[16 * 128 * 512];                       // gemm1 partials [split][b][col]
__device__ float g_part2[8 * 128 * 960];                        // gemm2 partials [split][b][col]
__device__ __align__(16) __nv_bfloat16 g_xh[128 * 64 * 512];    // x split-bf16
__device__ __align__(16) __nv_bfloat16 g_xl[128 * 64 * 512];
__device__ __align__(16) __nv_bfloat16 g_WcT_h[512 * 1024];     // Wc^T [n][k]
__device__ __align__(16) __nv_bfloat16 g_WcT_l[512 * 1024];
__device__ __align__(16) __nv_bfloat16 g_WkT_h[960 * 512];      // Wk^T [n][k], rows>=926 zero
__device__ __align__(16) __nv_bfloat16 g_WkT_l[960 * 512];
__device__ __align__(16) __nv_bfloat16 g_acth[128 * 512];       // tanh activations split-bf16
__device__ __align__(16) __nv_bfloat16 g_actl[128 * 512];
__device__ __align__(16) __nv_bfloat16 g_rvh[128 * 512];        // read vectors split-bf16
__device__ __align__(16) __nv_bfloat16 g_rvl[128 * 512];
__device__ unsigned g_barrier;

// ---------------- helpers ----------------
__device__ __forceinline__ uint32_t smem_u32(const void* p) {
    uint32_t a;
    asm("{ .reg .u64 t; cvta.to.shared.u64 t, %1; cvt.u32.u64 %0, t; }" : "=r"(a) : "l"(p));
    return a;
}
__device__ __forceinline__ void ldmatrix_x4(uint32_t& r0, uint32_t& r1, uint32_t& r2, uint32_t& r3, uint32_t addr) {
    asm volatile("ldmatrix.sync.aligned.m8n8.x4.shared.b16 {%0,%1,%2,%3}, [%4];"
                 : "=r"(r0), "=r"(r1), "=r"(r2), "=r"(r3) : "r"(addr));
}
__device__ __forceinline__ void mma_bf16(float* c, const uint32_t* a, uint32_t b0, uint32_t b1) {
    asm volatile("mma.sync.aligned.m16n8k16.row.col.f32.bf16.bf16.f32 "
                 "{%0,%1,%2,%3}, {%4,%5,%6,%7}, {%8,%9}, {%0,%1,%2,%3};"
                 : "+f"(c[0]), "+f"(c[1]), "+f"(c[2]), "+f"(c[3])
                 : "r"(a[0]), "r"(a[1]), "r"(a[2]), "r"(a[3]), "r"(b0), "r"(b1));
}
static __device__ __forceinline__ void bf16_split(float v, __nv_bfloat16& h, __nv_bfloat16& l) {
    h = __float2bfloat16(v);
    l = __float2bfloat16(v - __bfloat162float(h));
}

// ---------------- prep kernels ----------------
__global__ void prep_x_kernel(const float* __restrict__ x) {
    int i = blockIdx.x * blockDim.x + threadIdx.x;
    int st = gridDim.x * blockDim.x;
    for (int j = i; j < 128 * 64 * 512; j += st) {
        __nv_bfloat16 h, l; bf16_split(x[j], h, l);
        g_xh[j] = h; g_xl[j] = l;
    }
    for (int j = i; j < 128 * 512; j += st) {
        g_rvh[j] = __float2bfloat16(0.0f);
        g_rvl[j] = __float2bfloat16(0.0f);
    }
    if (i == 0) g_barrier = 0u;
}
__global__ void prep_w_kernel(const float* __restrict__ Wc, const float* __restrict__ Wk) {
    int i = blockIdx.x * blockDim.x + threadIdx.x;
    int st = gridDim.x * blockDim.x;
    for (int j = i; j < 512 * 1024; j += st) {
        int n = j >> 10, k = j & 1023;
        __nv_bfloat16 h, l; bf16_split(Wc[k * 512 + n], h, l);
        g_WcT_h[j] = h; g_WcT_l[j] = l;
    }
    for (int j = i; j < 960 * 512; j += st) {
        int n = j >> 9, k = j & 511;
        float v = (n < 926) ? Wk[k * 926 + n] : 0.0f;
        __nv_bfloat16 h, l; bf16_split(v, h, l);
        g_WkT_h[j] = h; g_WkT_l[j] = l;
    }
}

// ---------------- counter grid barrier ----------------
__device__ __forceinline__ void grid_sync(unsigned target) {
    __syncthreads();
    if (threadIdx.x == 0) {
        unsigned* bar = &g_barrier;
        asm volatile("red.release.gpu.global.add.u32 [%0], 1;" :: "l"(bar) : "memory");
        unsigned v;
        do {
            asm volatile("ld.relaxed.gpu.global.b32 %0, [%1];" : "=r"(v) : "l"(bar) : "memory");
        } while (v < target);
        asm volatile("fence.acq_rel.gpu;" ::: "memory");
    }
    __syncthreads();
}

// ---------------- tile staging (row stride 144 B = 72 bf16; 8 quads/row) ----------------
__device__ __forceinline__ void stage_A144(const __nv_bfloat16* __restrict__ srcH,
                                           const __nv_bfloat16* __restrict__ srcL,
                                           size_t rstride, char* tAh, char* tAl, int tid) {
#pragma unroll
    for (int it = 0; it < 2; it++) {
        int q = tid + it * 512;            // 0..1023
        int r = q >> 3, qq = q & 7;        // 128 rows x 8 quads
        uint4 vh = *(const uint4*)((const char*)(srcH + (size_t)r * rstride) + qq * 16);
        uint4 vl = *(const uint4*)((const char*)(srcL + (size_t)r * rstride) + qq * 16);
        *(uint4*)(tAh + r * 144 + qq * 16) = vh;
        *(uint4*)(tAl + r * 144 + qq * 16) = vl;
    }
}
__device__ __forceinline__ void stage_B144(const __nv_bfloat16* __restrict__ srcH,
                                           const __nv_bfloat16* __restrict__ srcL,
                                           size_t rstride, char* tBh, char* tBl, int tid) {
    int r = tid >> 3, qq = tid & 7;        // 64 rows x 8 quads = 512 quads
    uint4 vh = *(const uint4*)((const char*)(srcH + (size_t)r * rstride) + qq * 16);
    uint4 vl = *(const uint4*)((const char*)(srcL + (size_t)r * rstride) + qq * 16);
    *(uint4*)(tBh + r * 144 + qq * 16) = vh;
    *(uint4*)(tBl + r * 144 + qq * 16) = vl;
}

// ---------------- HMMA 128x64 tile, K=64, 3 passes (hh, lh, hl) ----------------
// 16 warps: grid 8(M) x 2(N), warp tile 16x32, A fragments register-cached.
__device__ __forceinline__ void gemm_tile_hmma(
    uint32_t aAh, uint32_t aAl, uint32_t aBh, uint32_t aBl,
    float* __restrict__ dst, int ldw, int lane, int wid) {
    const int wm = (wid & 7) * 16;
    const int wn = (wid >> 3) * 32;
    const uint32_t aBase = (uint32_t)(wm + (lane & 15)) * 144u + (uint32_t)((lane >> 4) * 16);
    const int l8 = lane & 7, sel = lane >> 3;
    const uint32_t bBase = (uint32_t)(wn + l8 + ((sel >> 1) * 8)) * 144u + (uint32_t)((sel & 1) * 16);

    uint32_t Ah[4][4], Al[4][4];
#pragma unroll
    for (int ks = 0; ks < 4; ks++) {
        ldmatrix_x4(Ah[ks][0], Ah[ks][1], Ah[ks][2], Ah[ks][3], aAh + aBase + ks * 32);
        ldmatrix_x4(Al[ks][0], Al[ks][1], Al[ks][2], Al[ks][3], aAl + aBase + ks * 32);
    }

    float acc[4][4];
#pragma unroll
    for (int nf2 = 0; nf2 < 4; nf2++)
#pragma unroll
        for (int i = 0; i < 4; i++) acc[nf2][i] = 0.0f;

#pragma unroll
    for (int p = 0; p < 3; p++) {
        uint32_t aB = (p == 2) ? aBl : aBh;
        const uint32_t (*A)[4] = (p == 1) ? Al : Ah;
#pragma unroll
        for (int ks = 0; ks < 4; ks++) {
#pragma unroll
            for (int nf = 0; nf < 2; nf++) {
                uint32_t b0, b1, b2, b3;
                ldmatrix_x4(b0, b1, b2, b3, aB + bBase + nf * (16 * 144) + ks * 32);
                mma_bf16(acc[nf * 2 + 0], A[ks], b0, b1);
                mma_bf16(acc[nf * 2 + 1], A[ks], b2, b3);
            }
        }
    }
    const int row = wm + (lane >> 2);
    const int colb = (lane & 3) * 2;
#pragma unroll
    for (int nf2 = 0; nf2 < 4; nf2++) {
        int col = wn + nf2 * 8 + colb;
        *(float2*)&dst[(size_t)row * ldw + col] = make_float2(acc[nf2][0], acc[nf2][1]);
        *(float2*)&dst[(size_t)(row + 8) * ldw + col] = make_float2(acc[nf2][2], acc[nf2][3]);
    }
}

// ---------------- the persistent kernel (512 threads, 128 CTAs) ----------------
// Mem padded to 132 floats/row: 16B-aligned rows, stride 33 granules -> conflict-free.
__global__ void __launch_bounds__(512) ntm_persistent(
    const float* __restrict__ bc, const float* __restrict__ bk,
    float* __restrict__ dout) {
    extern __shared__ float smem[];
    float* sM   = smem;            // 128*132 = 16896 floats (Mem, persistent)
    float* s_w  = smem + 16896;    // 640 floats (rw[4], ww[1], persistent)
    float* s_cn = smem + 17536;    // 512 floats (colnorm quarter-partials, persistent)

    uint32_t base_u32 = smem_u32(smem);
    uint32_t tiles_u32 = (base_u32 + 18048u * 4u + 1023u) & ~1023u;
    char* tiles = (char*)smem + (tiles_u32 - base_u32);
    char* tAh  = tiles;              uint32_t aAh  = tiles_u32;
    char* tAl  = tiles + 18432;      uint32_t aAl  = tiles_u32 + 18432;
    char* tB1h = tiles + 36864;      uint32_t aB1h = tiles_u32 + 36864;
    char* tB1l = tiles + 46080;      uint32_t aB1l = tiles_u32 + 46080;
    char* tB2h = tiles + 55296;      uint32_t aB2h = tiles_u32 + 55296;
    char* tB2l = tiles + 64512;      uint32_t aB2l = tiles_u32 + 64512;
    float* scratch = (float*)tAh;    // heads scratch aliases A tiles only (dead during heads)

    const int tid = threadIdx.x;
    const int wid = tid >> 5, lane = tid & 31;
    const int e = blockIdx.x;

    // per-CTA state init
    for (int i = tid; i < 128 * 128; i += 512) {
        int n = i >> 7, m = i & 127;
        sM[n * 132 + m] = (n == 64) ? 1.0f : 0.0f;
    }
    for (int i = tid; i < 640; i += 512) s_w[i] = 0.0f;
    __syncthreads();
    {
        int m = tid & 127, qt = tid >> 7;
        float cs = 0.0f;
        int n0 = qt * 32;
#pragma unroll 8
        for (int n = n0; n < n0 + 32; n++) { float v = sM[n * 132 + m]; cs += v * v; }
        s_cn[qt * 128 + m] = cs;
    }

    // tile coordinates
    const int g1_n0 = (e & 7) * 64;          // 8 coltiles
    const int g1_sp = e >> 3;                // 16 K-splits (K slice 64)
    const int g1_k0 = g1_sp * 64;
    const int g2_n0 = (e % 15) * 64;         // 15 coltiles (960)
    const int g2_sp = e / 15;                // 8 K-splits
    const int g2_k0 = g2_sp * 64;

    // resident B tiles (step-invariant weights; prep complete via stream order)
    stage_B144(g_WcT_h + (size_t)g1_n0 * 1024 + g1_k0, g_WcT_l + (size_t)g1_n0 * 1024 + g1_k0,
               1024, tB1h, tB1l, tid);
    if (e < 120)
        stage_B144(g_WkT_h + (size_t)g2_n0 * 512 + g2_k0, g_WkT_l + (size_t)g2_n0 * 512 + g2_k0,
                   512, tB2h, tB2l, tid);
    __syncthreads();

    unsigned nsync = 0;

    for (int t = 0; t < 64; t++) {
        // =========== GEMM1 (HMMA): part1 = [x_t | rv] @ Wc (B resident) ===========
        {
            const __nv_bfloat16 *ah, *al;
            size_t rs;
            if (g1_k0 < 512) { ah = g_xh + (size_t)t * 512 + g1_k0; al = g_xl + (size_t)t * 512 + g1_k0; rs = 64 * 512; }
            else             { ah = g_rvh + (g1_k0 - 512);          al = g_rvl + (g1_k0 - 512);          rs = 512; }
            stage_A144(ah, al, rs, tAh, tAl, tid);
            __syncthreads();
            gemm_tile_hmma(aAh, aAl, aB1h, aB1l,
                           &g_part1[(size_t)(g1_sp * 128) * 512 + g1_n0], 512, lane, wid);
        }
        grid_sync(++nsync * NB);

        // =========== ACT: tanh(sum 16 partials + bc) ===========
        {
            int j = tid;   // 512 threads x 1 col
            float s = bc[j];
#pragma unroll
            for (int sp = 0; sp < 16; sp++) s += g_part1[(size_t)(sp * 128 + e) * 512 + j];
            float v = tanhf(s);
            dout[((size_t)e * 64 + t) * 512 + j] = v;
            __nv_bfloat16 h, l; bf16_split(v, h, l);
            g_acth[e * 512 + j] = h;
            g_actl[e * 512 + j] = l;
        }
        grid_sync(++nsync * NB);

        // =========== GEMM2 (HMMA): part2 = act @ Wk (B resident) ===========
        if (e < 120) {
            stage_A144(g_acth + g2_k0, g_actl + g2_k0, 512, tAh, tAl, tid);
            __syncthreads();
            gemm_tile_hmma(aAh, aAl, aB2h, aB2l,
                           &g_part2[(size_t)(g2_sp * 128) * 960 + g2_n0], 960, lane, wid);
        }
        grid_sync(++nsync * NB);

        // =========== HEADS (per-batch, SMEM-resident Mem, vectorized) ===========
        {
            float* s_instr = scratch;           // 928
            float* s_rsn   = scratch + 928;     // 128
            float* s_q     = scratch + 1056;    // 640
            float* s_p2    = scratch + 1696;    // 5*512 = 2560
            float* s_wi    = scratch + 4256;    // 640 (total 4896 < 9216 floats of A tiles)

            for (int j = tid; j < 926; j += 512) {
                float s = bk[j];
#pragma unroll
                for (int sp = 0; sp < 8; sp++) s += g_part2[(size_t)(sp * 128 + e) * 960 + j];
                s_instr[j] = s;
            }
            if (tid < 128)
                s_rsn[tid] = rsqrtf(fmaxf(s_cn[tid] + s_cn[128 + tid] + s_cn[256 + tid] + s_cn[384 + tid], 1e-12f));
            __syncthreads();

            // key l2-norm + q (warp h = head h)
            if (wid < 5) {
                int basei = (wid < 4) ? wid * 134 : 536;
                float kv[4];
                float ks = 0.0f;
#pragma unroll
                for (int j = 0; j < 4; j++) { int m = lane * 4 + j; kv[j] = s_instr[basei + m]; ks += kv[j] * kv[j]; }
#pragma unroll
                for (int o = 16; o > 0; o >>= 1) ks += __shfl_xor_sync(0xffffffffu, ks, o);
                float rk = rsqrtf(fmaxf(ks, 1e-12f));
#pragma unroll
                for (int j = 0; j < 4; j++) { int m = lane * 4 + j; s_q[wid * 128 + m] = kv[j] * rk * s_rsn[m]; }
            }
            __syncthreads();

            // sim matvec (512 threads: n x quarter), float4 row + float4 broadcast q
            {
                int n = tid & 127, qt = tid >> 7;
                const float* row = &sM[n * 132];
                int m0 = qt * 32;
                float a0 = 0, a1 = 0, a2 = 0, a3 = 0, a4 = 0;
#pragma unroll
                for (int mc = 0; mc < 32; mc += 4) {
                    int m = m0 + mc;
                    float4 rv4 = *(const float4*)&row[m];
                    float4 q0 = *(const float4*)&s_q[m];
                    float4 q1 = *(const float4*)&s_q[128 + m];
                    float4 q2 = *(const float4*)&s_q[256 + m];
                    float4 q3 = *(const float4*)&s_q[384 + m];
                    float4 q4 = *(const float4*)&s_q[512 + m];
                    a0 += rv4.x * q0.x + rv4.y * q0.y + rv4.z * q0.z + rv4.w * q0.w;
                    a1 += rv4.x * q1.x + rv4.y * q1.y + rv4.z * q1.z + rv4.w * q1.w;
                    a2 += rv4.x * q2.x + rv4.y * q2.y + rv4.z * q2.z + rv4.w * q2.w;
                    a3 += rv4.x * q3.x + rv4.y * q3.y + rv4.z * q3.z + rv4.w * q3.w;
                    a4 += rv4.x * q4.x + rv4.y * q4.y + rv4.z * q4.z + rv4.w * q4.w;
                }
                s_p2[0 * 512 + qt * 128 + n] = a0;
                s_p2[1 * 512 + qt * 128 + n] = a1;
                s_p2[2 * 512 + qt * 128 + n] = a2;
                s_p2[3 * 512 + qt * 128 + n] = a3;
                s_p2[4 * 512 + qt * 128 + n] = a4;
            }
            __syncthreads();

            // per-head chain (warp h), shuffle-only reductions
            if (wid < 5) {
                int basei = (wid < 4) ? wid * 134 : 536;
                float beta = expf(s_instr[basei + 128]);
                float gg = 1.0f / (1.0f + expf(-s_instr[basei + 129]));
                float a0 = s_instr[basei + 130], a1 = s_instr[basei + 131], a2 = s_instr[basei + 132];
                float mxs = fmaxf(a0, fmaxf(a1, a2));
                float e0 = expf(a0 - mxs), e1 = expf(a1 - mxs), e2 = expf(a2 - mxs);
                float esi = 1.0f / (e0 + e1 + e2);
                float sh0 = e0 * esi, sh1 = e1 * esi, sh2 = e2 * esi;
                float xt = s_instr[basei + 133];
                float tpow = fmaxf(xt, 0.0f) + log1pf(expf(-fabsf(xt))) + 1.0f;

                float vv[4];
                float mx = -3.4e38f;
#pragma unroll
                for (int j = 0; j < 4; j++) {
                    int n = lane * 4 + j;
                    vv[j] = (s_p2[wid * 512 + n] + s_p2[wid * 512 + 128 + n]
                           + s_p2[wid * 512 + 256 + n] + s_p2[wid * 512 + 384 + n]) * beta;
                    mx = fmaxf(mx, vv[j]);
                }
#pragma unroll
                for (int o = 16; o > 0; o >>= 1) mx = fmaxf(mx, __shfl_xor_sync(0xffffffffu, mx, o));
                float ee[4], se = 0.0f;
#pragma unroll
                for (int j = 0; j < 4; j++) { ee[j] = expf(vv[j] - mx); se += ee[j]; }
#pragma unroll
                for (int o = 16; o > 0; o >>= 1) se += __shfl_xor_sync(0xffffffffu, se, o);
                float sei = 1.0f / se;
#pragma unroll
                for (int j = 0; j < 4; j++) {
                    int n = lane * 4 + j;
                    float wold = s_w[wid * 128 + n];
                    s_wi[wid * 128 + n] = ee[j] * sei * gg + wold * (1.0f - gg);
                }
                __syncwarp();
                float pp[4], ps = 0.0f;
#pragma unroll
                for (int j = 0; j < 4; j++) {
                    int n = lane * 4 + j;
                    float ws = sh0 * s_wi[wid * 128 + ((n + 127) & 127)]
                             + sh1 * s_wi[wid * 128 + n]
                             + sh2 * s_wi[wid * 128 + ((n + 1) & 127)];
                    pp[j] = powf(ws, tpow);
                    ps += pp[j];
                }
#pragma unroll
                for (int o = 16; o > 0; o >>= 1) ps += __shfl_xor_sync(0xffffffffu, ps, o);
                float psi = 1.0f / (ps + 1e-12f);
#pragma unroll
                for (int j = 0; j < 4; j++) {
                    int n = lane * 4 + j;
                    s_w[wid * 128 + n] = pp[j] * psi;
                }
            }
            __syncthreads();

            // erase/add (W=1) + rv partials + fused colnorm; float4 broadcast weights
            {
                int m = tid & 127, qt = tid >> 7;
                float em = s_instr[670 + m];
                float am = s_instr[798 + m];
                float r0 = 0, r1 = 0, r2 = 0, r3 = 0, cs = 0;
                int n0 = qt * 32;
#pragma unroll
                for (int nc = n0; nc < n0 + 32; nc += 4) {
                    float4 ww4 = *(const float4*)&s_w[512 + nc];
                    float4 w0 = *(const float4*)&s_w[nc];
                    float4 w1 = *(const float4*)&s_w[128 + nc];
                    float4 w2 = *(const float4*)&s_w[256 + nc];
                    float4 w3 = *(const float4*)&s_w[384 + nc];
                    const float* ww = &ww4.x;
                    const float* p0 = &w0.x; const float* p1 = &w1.x;
                    const float* p2 = &w2.x; const float* p3 = &w3.x;
#pragma unroll
                    for (int u = 0; u < 4; u++) {
                        int n = nc + u;
                        float Mv = sM[n * 132 + m];
                        Mv = Mv * (1.0f - ww[u] * em) + ww[u] * am;
                        sM[n * 132 + m] = Mv;
                        cs += Mv * Mv;
                        r0 += Mv * p0[u]; r1 += Mv * p1[u];
                        r2 += Mv * p2[u]; r3 += Mv * p3[u];
                    }
                }
                s_cn[qt * 128 + m] = cs;
                s_p2[0 * 512 + qt * 128 + m] = r0;
                s_p2[1 * 512 + qt * 128 + m] = r1;
                s_p2[2 * 512 + qt * 128 + m] = r2;
                s_p2[3 * 512 + qt * 128 + m] = r3;
            }
            __syncthreads();
            if (tid < 128) {
#pragma unroll
                for (int r = 0; r < 4; r++) {
                    float rv = s_p2[r * 512 + tid] + s_p2[r * 512 + 128 + tid]
                             + s_p2[r * 512 + 256 + tid] + s_p2[r * 512 + 384 + tid];
                    __nv_bfloat16 h, l; bf16_split(rv, h, l);
                    g_rvh[e * 512 + r * 128 + tid] = h;
                    g_rvl[e * 512 + r * 128 + tid] = l;
                }
            }
        }
        grid_sync(++nsync * NB);
    }
}

// ---------------- launch ----------------
extern "C" void kernel_launch(void* const* d_in, const int* in_sizes, int n_in,
                              void* d_out, int out_size) {
    const float *x = nullptr, *Wc = nullptr, *bc = nullptr, *Wk = nullptr, *bk = nullptr;
    for (int i = 0; i < n_in; i++) {
        switch (in_sizes[i]) {
            case 128 * 64 * 512: x  = (const float*)d_in[i]; break;
            case 1024 * 512:     Wc = (const float*)d_in[i]; break;
            case 512:            bc = (const float*)d_in[i]; break;
            case 512 * 926:      Wk = (const float*)d_in[i]; break;
            case 926:            bk = (const float*)d_in[i]; break;
        }
    }

    // smem: 18048 floats persistent + align + 73728B tiles (A + B1 + B2 resident)
    const int SMEM = 18048 * 4 + 1024 + 73728;  // 146944 B
    cudaFuncSetAttribute(ntm_persistent, cudaFuncAttributeMaxDynamicSharedMemorySize, SMEM);

    prep_x_kernel<<<2048, 256>>>(x);
    prep_w_kernel<<<1024, 256>>>(Wc, Wk);
    ntm_persistent<<<128, 512, SMEM>>>(bc, bk, (float*)d_out);
}